// round 3
// baseline (speedup 1.0000x reference)
#include <cuda_runtime.h>
#include <math.h>

#define NN 100000
#define HID 128
#define NE 1600000
#define NFILT 64
#define TS 2048
#define CUT 8.0f

// scratch: segment-sum accumulator + per-edge-scale lookup table
__device__ float g_agg[NN * HID];
__device__ float g_table[TS];

// ---------------------------------------------------------------------------
// Kernel 1: build s(w) lookup table.  s(w) = cut(w) * (sum_k tanh((0.25w-1)*Wf1k+bf1k)*wsum_k + bsum)
// ---------------------------------------------------------------------------
__global__ void k_table(const float* __restrict__ Wf1, const float* __restrict__ bf1,
                        const float* __restrict__ Wf2, const float* __restrict__ bf2) {
    __shared__ float wsum[NFILT];
    __shared__ float bsum;
    int t = threadIdx.x;
    if (t < NFILT) {
        float s = 0.f;
        for (int j = 0; j < NFILT; j++) s += Wf2[t * NFILT + j];
        wsum[t] = s;
    }
    if (t == 0) {
        float s = 0.f;
        for (int j = 0; j < NFILT; j++) s += bf2[j];
        bsum = s;
    }
    __syncthreads();
    for (int i = t; i < TS; i += blockDim.x) {
        float w = (float)i * (CUT / (float)(TS - 1));
        float scaled = w * (2.0f / CUT) - 1.0f;
        float acc = bsum;
        for (int k = 0; k < NFILT; k++)
            acc += tanhf(scaled * Wf1[k] + bf1[k]) * wsum[k];
        float cutv = 0.5f * (cosf(w * 3.14159265358979323846f / CUT) + 1.0f);
        if (w > CUT) cutv = 0.0f;
        g_table[i] = acc * cutv;
    }
}

// ---------------------------------------------------------------------------
// Kernel 2: zero the accumulator
// ---------------------------------------------------------------------------
__global__ void k_zero() {
    int i = blockIdx.x * blockDim.x + threadIdx.x;
    const int n4 = NN * HID / 4;
    if (i < n4) reinterpret_cast<float4*>(g_agg)[i] = make_float4(0.f, 0.f, 0.f, 0.f);
}

// ---------------------------------------------------------------------------
// Kernel 3: edge scatter.  Each warp processes a chunk of 32 edges:
// lanes load metadata coalesced, then per edge the warp gathers x[col] (128
// floats, float4/lane) and vector-atomicAdds into agg[row].
// ---------------------------------------------------------------------------
__global__ void __launch_bounds__(256) k_scatter(const float* __restrict__ x,
                                                 const int* __restrict__ ei,
                                                 const float* __restrict__ ew) {
    const int lane = threadIdx.x & 31;
    const int gwarp = (blockIdx.x * blockDim.x + threadIdx.x) >> 5;
    const int nwarps = (gridDim.x * blockDim.x) >> 5;
    const int nchunks = NE / 32;  // 50000, exact

    for (int c = gwarp; c < nchunks; c += nwarps) {
        int e = c * 32 + lane;
        int row = __ldg(ei + e);
        int col = __ldg(ei + NE + e);
        float w = __ldg(ew + e);
        // table lookup with linear interpolation
        float tp = w * ((float)(TS - 1) / CUT);
        int ti = (int)tp;
        ti = ti < 0 ? 0 : (ti > TS - 2 ? TS - 2 : ti);
        float fr = tp - (float)ti;
        float t0 = __ldg(g_table + ti);
        float t1 = __ldg(g_table + ti + 1);
        float s = t0 + fr * (t1 - t0);

#pragma unroll 4
        for (int j = 0; j < 32; j++) {
            int r  = __shfl_sync(0xffffffffu, row, j);
            int cc = __shfl_sync(0xffffffffu, col, j);
            float sj = __shfl_sync(0xffffffffu, s, j);
            float4 v = __ldg(reinterpret_cast<const float4*>(x + (size_t)cc * HID) + lane);
            v.x *= sj; v.y *= sj; v.z *= sj; v.w *= sj;
            atomicAdd(reinterpret_cast<float4*>(g_agg + (size_t)r * HID) + lane, v);
        }
    }
}

// ---------------------------------------------------------------------------
// Kernel 4: fused MLP  out = BN( softplus(agg@W1+b1) @ W2 + b2 )
// 512 threads, 64-node tile. smem: W tile (64KB) + A/H tile (32KB, reused).
// Thread (warp w, lane l) owns nodes m = w*4+i (i<4) and outputs j = l*4..l*4+3.
// ---------------------------------------------------------------------------
__device__ __forceinline__ float softplusf(float z) {
    return fmaxf(z, 0.f) + log1pf(__expf(-fabsf(z)));
}

__global__ void __launch_bounds__(512) k_mlp(const float* __restrict__ Wi1,
                                             const float* __restrict__ bi1,
                                             const float* __restrict__ Wi2,
                                             const float* __restrict__ bi2,
                                             const float* __restrict__ gamma,
                                             const float* __restrict__ beta,
                                             const float* __restrict__ mmean,
                                             const float* __restrict__ mvar,
                                             float* __restrict__ out) {
    extern __shared__ float smem[];
    float4* sW4 = reinterpret_cast<float4*>(smem);                 // 4096 float4 (W, 64KB)
    float4* sA4 = reinterpret_cast<float4*>(smem + HID * HID);     // 2048 float4 (A/H, 32KB)

    const int t = threadIdx.x;
    const int lane = t & 31;
    const int warp = t >> 5;
    const int m0 = blockIdx.x * 64;

    // load W1 (128x128 f32 = 4096 float4)
    const float4* W1_4 = reinterpret_cast<const float4*>(Wi1);
#pragma unroll
    for (int i = 0; i < 8; i++) sW4[t + i * 512] = __ldg(W1_4 + t + i * 512);

    // load agg tile (64 rows x 32 float4)
#pragma unroll
    for (int i = 0; i < 4; i++) {
        int idx = t + i * 512;          // 0..2047
        int m = idx >> 5;
        int k4 = idx & 31;
        int node = m0 + m;
        float4 v = make_float4(0.f, 0.f, 0.f, 0.f);
        if (node < NN)
            v = reinterpret_cast<const float4*>(g_agg)[(size_t)node * 32 + k4];
        sA4[idx] = v;
    }
    __syncthreads();

    float4 acc[4];
#pragma unroll
    for (int i = 0; i < 4; i++) acc[i] = make_float4(0.f, 0.f, 0.f, 0.f);

    // GEMM1: acc[m_i][j-quad] = sum_k A[m,k] * W1[k,j]
    for (int k4 = 0; k4 < 32; k4++) {
        float4 w0 = sW4[(k4 * 4 + 0) * 32 + lane];
        float4 w1 = sW4[(k4 * 4 + 1) * 32 + lane];
        float4 w2 = sW4[(k4 * 4 + 2) * 32 + lane];
        float4 w3 = sW4[(k4 * 4 + 3) * 32 + lane];
#pragma unroll
        for (int i = 0; i < 4; i++) {
            float4 a = sA4[(warp * 4 + i) * 32 + k4];
            acc[i].x = fmaf(a.x, w0.x, acc[i].x); acc[i].y = fmaf(a.x, w0.y, acc[i].y);
            acc[i].z = fmaf(a.x, w0.z, acc[i].z); acc[i].w = fmaf(a.x, w0.w, acc[i].w);
            acc[i].x = fmaf(a.y, w1.x, acc[i].x); acc[i].y = fmaf(a.y, w1.y, acc[i].y);
            acc[i].z = fmaf(a.y, w1.z, acc[i].z); acc[i].w = fmaf(a.y, w1.w, acc[i].w);
            acc[i].x = fmaf(a.z, w2.x, acc[i].x); acc[i].y = fmaf(a.z, w2.y, acc[i].y);
            acc[i].z = fmaf(a.z, w2.z, acc[i].z); acc[i].w = fmaf(a.z, w2.w, acc[i].w);
            acc[i].x = fmaf(a.w, w3.x, acc[i].x); acc[i].y = fmaf(a.w, w3.y, acc[i].y);
            acc[i].z = fmaf(a.w, w3.z, acc[i].z); acc[i].w = fmaf(a.w, w3.w, acc[i].w);
        }
    }

    // softplus(acc + b1) -> h
    float4 b1 = __ldg(reinterpret_cast<const float4*>(bi1) + lane);
    float4 h[4];
#pragma unroll
    for (int i = 0; i < 4; i++) {
        h[i].x = softplusf(acc[i].x + b1.x);
        h[i].y = softplusf(acc[i].y + b1.y);
        h[i].z = softplusf(acc[i].z + b1.z);
        h[i].w = softplusf(acc[i].w + b1.w);
    }
    __syncthreads();   // all reads of sA4 / sW4 done

    // stash h into the A buffer; reload W buffer with W2
#pragma unroll
    for (int i = 0; i < 4; i++) sA4[(warp * 4 + i) * 32 + lane] = h[i];
    const float4* W2_4 = reinterpret_cast<const float4*>(Wi2);
#pragma unroll
    for (int i = 0; i < 8; i++) sW4[t + i * 512] = __ldg(W2_4 + t + i * 512);
    __syncthreads();

#pragma unroll
    for (int i = 0; i < 4; i++) acc[i] = make_float4(0.f, 0.f, 0.f, 0.f);

    // GEMM2
    for (int k4 = 0; k4 < 32; k4++) {
        float4 w0 = sW4[(k4 * 4 + 0) * 32 + lane];
        float4 w1 = sW4[(k4 * 4 + 1) * 32 + lane];
        float4 w2 = sW4[(k4 * 4 + 2) * 32 + lane];
        float4 w3 = sW4[(k4 * 4 + 3) * 32 + lane];
#pragma unroll
        for (int i = 0; i < 4; i++) {
            float4 a = sA4[(warp * 4 + i) * 32 + k4];
            acc[i].x = fmaf(a.x, w0.x, acc[i].x); acc[i].y = fmaf(a.x, w0.y, acc[i].y);
            acc[i].z = fmaf(a.x, w0.z, acc[i].z); acc[i].w = fmaf(a.x, w0.w, acc[i].w);
            acc[i].x = fmaf(a.y, w1.x, acc[i].x); acc[i].y = fmaf(a.y, w1.y, acc[i].y);
            acc[i].z = fmaf(a.y, w1.z, acc[i].z); acc[i].w = fmaf(a.y, w1.w, acc[i].w);
            acc[i].x = fmaf(a.z, w2.x, acc[i].x); acc[i].y = fmaf(a.z, w2.y, acc[i].y);
            acc[i].z = fmaf(a.z, w2.z, acc[i].z); acc[i].w = fmaf(a.z, w2.w, acc[i].w);
            acc[i].x = fmaf(a.w, w3.x, acc[i].x); acc[i].y = fmaf(a.w, w3.y, acc[i].y);
            acc[i].z = fmaf(a.w, w3.z, acc[i].z); acc[i].w = fmaf(a.w, w3.w, acc[i].w);
        }
    }

    // bias + batchnorm (inference), write out
    float4 b2 = __ldg(reinterpret_cast<const float4*>(bi2) + lane);
    float4 gm = __ldg(reinterpret_cast<const float4*>(gamma) + lane);
    float4 bt = __ldg(reinterpret_cast<const float4*>(beta) + lane);
    float4 mn = __ldg(reinterpret_cast<const float4*>(mmean) + lane);
    float4 vr = __ldg(reinterpret_cast<const float4*>(mvar) + lane);
    float4 sc, sh;
    sc.x = gm.x * rsqrtf(vr.x + 1e-3f); sh.x = bt.x - mn.x * sc.x;
    sc.y = gm.y * rsqrtf(vr.y + 1e-3f); sh.y = bt.y - mn.y * sc.y;
    sc.z = gm.z * rsqrtf(vr.z + 1e-3f); sh.z = bt.z - mn.z * sc.z;
    sc.w = gm.w * rsqrtf(vr.w + 1e-3f); sh.w = bt.w - mn.w * sc.w;

#pragma unroll
    for (int i = 0; i < 4; i++) {
        int node = m0 + warp * 4 + i;
        if (node < NN) {
            float4 o;
            o.x = fmaf(acc[i].x + b2.x, sc.x, sh.x);
            o.y = fmaf(acc[i].y + b2.y, sc.y, sh.y);
            o.z = fmaf(acc[i].z + b2.z, sc.z, sh.z);
            o.w = fmaf(acc[i].w + b2.w, sc.w, sh.w);
            reinterpret_cast<float4*>(out)[(size_t)node * 32 + lane] = o;
        }
    }
}

// ---------------------------------------------------------------------------
extern "C" void kernel_launch(void* const* d_in, const int* in_sizes, int n_in,
                              void* d_out, int out_size) {
    const float* x    = (const float*)d_in[0];
    const int*   ei   = (const int*)d_in[1];
    const float* ew   = (const float*)d_in[2];
    // d_in[3] = edge_attr (unused by reference)
    const float* Wf1  = (const float*)d_in[4];
    const float* bf1  = (const float*)d_in[5];
    const float* Wf2  = (const float*)d_in[6];
    const float* bf2  = (const float*)d_in[7];
    const float* Wi1  = (const float*)d_in[8];
    const float* bi1  = (const float*)d_in[9];
    const float* Wi2  = (const float*)d_in[10];
    const float* bi2  = (const float*)d_in[11];
    const float* gm   = (const float*)d_in[12];
    const float* bt   = (const float*)d_in[13];
    const float* mn   = (const float*)d_in[14];
    const float* vr   = (const float*)d_in[15];
    float* out = (float*)d_out;

    cudaFuncSetAttribute(k_mlp, cudaFuncAttributeMaxDynamicSharedMemorySize, 98304);

    k_table<<<1, 1024>>>(Wf1, bf1, Wf2, bf2);
    k_zero<<<(NN * HID / 4 + 255) / 256, 256>>>();
    k_scatter<<<1536, 256>>>(x, ei, ew);
    k_mlp<<<(NN + 63) / 64, 512, 98304>>>(Wi1, bi1, Wi2, bi2, gm, bt, mn, vr, out);
}

// round 5
// speedup vs baseline: 1.0319x; 1.0319x over previous
#include <cuda_runtime.h>
#include <math.h>

#define NN 100000
#define HID 128
#define NE 1600000
#define NFILT 64
#define TS 2048
#define CUT 8.0f

typedef unsigned long long u64;

// scratch: segment-sum accumulator + per-edge-scale lookup table
__device__ float g_agg[NN * HID];
__device__ float g_table[TS];

// ---------------------------------------------------------------------------
// packed f32x2 helpers (SASS FFMA2 — 2x fp32 throughput, PTX-only pattern)
// ---------------------------------------------------------------------------
__device__ __forceinline__ void ffma2(float2& d, u64 a, u64 b) {
    asm("fma.rn.f32x2 %0, %1, %2, %0;"
        : "+l"(*reinterpret_cast<u64*>(&d)) : "l"(a), "l"(b));
}
__device__ __forceinline__ u64 dup2(float s) {
    u64 r;
    asm("mov.b64 %0, {%1, %1};" : "=l"(r) : "r"(__float_as_uint(s)));
    return r;
}

// ---------------------------------------------------------------------------
// Kernel 1: build s(w) lookup table.
// s(w) = cut(w) * (sum_k tanh((0.25w-1)*Wf1k+bf1k)*rowsum(Wf2)k + sum(bf2))
// ---------------------------------------------------------------------------
__global__ void k_table(const float* __restrict__ Wf1, const float* __restrict__ bf1,
                        const float* __restrict__ Wf2, const float* __restrict__ bf2) {
    __shared__ float wsum[NFILT];
    __shared__ float bsum;
    int t = threadIdx.x;
    if (t < NFILT) {
        float s = 0.f;
        for (int j = 0; j < NFILT; j++) s += Wf2[t * NFILT + j];
        wsum[t] = s;
    }
    if (t == 0) {
        float s = 0.f;
        for (int j = 0; j < NFILT; j++) s += bf2[j];
        bsum = s;
    }
    __syncthreads();
    for (int i = t; i < TS; i += blockDim.x) {
        float w = (float)i * (CUT / (float)(TS - 1));
        float scaled = w * (2.0f / CUT) - 1.0f;
        float acc = bsum;
        for (int k = 0; k < NFILT; k++)
            acc += tanhf(scaled * Wf1[k] + bf1[k]) * wsum[k];
        float cutv = 0.5f * (cosf(w * 3.14159265358979323846f / CUT) + 1.0f);
        if (w > CUT) cutv = 0.0f;
        g_table[i] = acc * cutv;
    }
}

// ---------------------------------------------------------------------------
// Kernel 2: zero the accumulator
// ---------------------------------------------------------------------------
__global__ void k_zero() {
    int i = blockIdx.x * blockDim.x + threadIdx.x;
    const int n4 = NN * HID / 4;
    if (i < n4) reinterpret_cast<float4*>(g_agg)[i] = make_float4(0.f, 0.f, 0.f, 0.f);
}

// ---------------------------------------------------------------------------
// Kernel 3: edge scatter (L2-roofline bound; warp-per-32-edge-chunk,
// float4 vector atomics). Unchanged from R2 — measured at the LTS cap.
// ---------------------------------------------------------------------------
__global__ void __launch_bounds__(256) k_scatter(const float* __restrict__ x,
                                                 const int* __restrict__ ei,
                                                 const float* __restrict__ ew) {
    const int lane = threadIdx.x & 31;
    const int gwarp = (blockIdx.x * blockDim.x + threadIdx.x) >> 5;
    const int nwarps = (gridDim.x * blockDim.x) >> 5;
    const int nchunks = NE / 32;  // 50000, exact

    for (int c = gwarp; c < nchunks; c += nwarps) {
        int e = c * 32 + lane;
        int row = __ldg(ei + e);
        int col = __ldg(ei + NE + e);
        float w = __ldg(ew + e);
        float tp = w * ((float)(TS - 1) / CUT);
        int ti = (int)tp;
        ti = ti < 0 ? 0 : (ti > TS - 2 ? TS - 2 : ti);
        float fr = tp - (float)ti;
        float t0 = __ldg(g_table + ti);
        float t1 = __ldg(g_table + ti + 1);
        float s = t0 + fr * (t1 - t0);

#pragma unroll 4
        for (int j = 0; j < 32; j++) {
            int r  = __shfl_sync(0xffffffffu, row, j);
            int cc = __shfl_sync(0xffffffffu, col, j);
            float sj = __shfl_sync(0xffffffffu, s, j);
            float4 v = __ldg(reinterpret_cast<const float4*>(x + (size_t)cc * HID) + lane);
            v.x *= sj; v.y *= sj; v.z *= sj; v.w *= sj;
            atomicAdd(reinterpret_cast<float4*>(g_agg + (size_t)r * HID) + lane, v);
        }
    }
}

// ---------------------------------------------------------------------------
// Kernel 4: fused MLP  out = BN( softplus(agg@W1+b1) @ W2 + b2 )
// f32x2 packed-FMA version.
// Block = 256 threads (8 warps), tile = 64 nodes. Warp owns 8 rows; lane owns
// cols 4l..4l+3 as two f32x2 accumulator pairs. smem: W (64KB) + A/H (32KB).
// Per k: 16 FFMA2 (fma pipe, binding) + 8 dup movs (alu pipe) + 3 LDS (LSU).
// ---------------------------------------------------------------------------
__device__ __forceinline__ float softplusf(float z) {
    return fmaxf(z, 0.f) + log1pf(__expf(-fabsf(z)));
}

__device__ __forceinline__ void gemm_tile_f32x2(const ulonglong2* __restrict__ sWp,
                                                const float4* __restrict__ sA4,
                                                int warp, int lane,
                                                float2 acc[8][2]) {
#pragma unroll 1
    for (int k4 = 0; k4 < 32; k4++) {
        ulonglong2 w0 = sWp[(k4 * 4 + 0) * 32 + lane];
        ulonglong2 w1 = sWp[(k4 * 4 + 1) * 32 + lane];
        ulonglong2 w2 = sWp[(k4 * 4 + 2) * 32 + lane];
        ulonglong2 w3 = sWp[(k4 * 4 + 3) * 32 + lane];
#pragma unroll
        for (int i = 0; i < 8; i++) {
            float4 a = sA4[(warp * 8 + i) * 32 + k4];
            u64 d;
            d = dup2(a.x); ffma2(acc[i][0], d, w0.x); ffma2(acc[i][1], d, w0.y);
            d = dup2(a.y); ffma2(acc[i][0], d, w1.x); ffma2(acc[i][1], d, w1.y);
            d = dup2(a.z); ffma2(acc[i][0], d, w2.x); ffma2(acc[i][1], d, w2.y);
            d = dup2(a.w); ffma2(acc[i][0], d, w3.x); ffma2(acc[i][1], d, w3.y);
        }
    }
}

__global__ void __launch_bounds__(256, 2) k_mlp(const float* __restrict__ Wi1,
                                                const float* __restrict__ bi1,
                                                const float* __restrict__ Wi2,
                                                const float* __restrict__ bi2,
                                                const float* __restrict__ gamma,
                                                const float* __restrict__ beta,
                                                const float* __restrict__ mmean,
                                                const float* __restrict__ mvar,
                                                float* __restrict__ out) {
    extern __shared__ float smem[];
    float4*     sW4 = reinterpret_cast<float4*>(smem);            // W: 128x128 f32 (64KB)
    ulonglong2* sWp = reinterpret_cast<ulonglong2*>(smem);
    float4*     sA4 = reinterpret_cast<float4*>(smem + HID * HID);// A/H: 64x128 f32 (32KB)

    const int t = threadIdx.x;
    const int lane = t & 31;
    const int warp = t >> 5;
    const int m0 = blockIdx.x * 64;

    // load W1 (4096 float4, 16 per thread)
    const float4* W1_4 = reinterpret_cast<const float4*>(Wi1);
#pragma unroll
    for (int i = 0; i < 16; i++) sW4[t + i * 256] = __ldg(W1_4 + t + i * 256);

    // load agg tile (64 rows x 32 float4, 8 per thread)
#pragma unroll
    for (int i = 0; i < 8; i++) {
        int idx = t + i * 256;
        int m = idx >> 5, k4 = idx & 31;
        int node = m0 + m;
        float4 v = make_float4(0.f, 0.f, 0.f, 0.f);
        if (node < NN)
            v = reinterpret_cast<const float4*>(g_agg)[(size_t)node * 32 + k4];
        sA4[idx] = v;
    }
    __syncthreads();

    float2 acc[8][2];
#pragma unroll
    for (int i = 0; i < 8; i++) {
        acc[i][0] = make_float2(0.f, 0.f);
        acc[i][1] = make_float2(0.f, 0.f);
    }

    // GEMM1
    gemm_tile_f32x2(sWp, sA4, warp, lane, acc);

    // softplus(acc + b1) -> h, stash into own rows of the A buffer
    float4 b1 = __ldg(reinterpret_cast<const float4*>(bi1) + lane);
#pragma unroll
    for (int i = 0; i < 8; i++) {
        float4 h;
        h.x = softplusf(acc[i][0].x + b1.x);
        h.y = softplusf(acc[i][0].y + b1.y);
        h.z = softplusf(acc[i][1].x + b1.z);
        h.w = softplusf(acc[i][1].y + b1.w);
        sA4[(warp * 8 + i) * 32 + lane] = h;
    }
    __syncthreads();   // all warps done reading W1; h stores visible

    // load W2
    const float4* W2_4 = reinterpret_cast<const float4*>(Wi2);
#pragma unroll
    for (int i = 0; i < 16; i++) sW4[t + i * 256] = __ldg(W2_4 + t + i * 256);
    __syncthreads();

#pragma unroll
    for (int i = 0; i < 8; i++) {
        acc[i][0] = make_float2(0.f, 0.f);
        acc[i][1] = make_float2(0.f, 0.f);
    }

    // GEMM2
    gemm_tile_f32x2(sWp, sA4, warp, lane, acc);

    // bias + batchnorm (inference), write out
    float4 b2 = __ldg(reinterpret_cast<const float4*>(bi2) + lane);
    float4 gm = __ldg(reinterpret_cast<const float4*>(gamma) + lane);
    float4 bt = __ldg(reinterpret_cast<const float4*>(beta) + lane);
    float4 mn = __ldg(reinterpret_cast<const float4*>(mmean) + lane);
    float4 vr = __ldg(reinterpret_cast<const float4*>(mvar) + lane);
    float4 sc, sh;
    sc.x = gm.x * rsqrtf(vr.x + 1e-3f); sh.x = bt.x - mn.x * sc.x;
    sc.y = gm.y * rsqrtf(vr.y + 1e-3f); sh.y = bt.y - mn.y * sc.y;
    sc.z = gm.z * rsqrtf(vr.z + 1e-3f); sh.z = bt.z - mn.z * sc.z;
    sc.w = gm.w * rsqrtf(vr.w + 1e-3f); sh.w = bt.w - mn.w * sc.w;

#pragma unroll
    for (int i = 0; i < 8; i++) {
        int node = m0 + warp * 8 + i;
        if (node < NN) {
            float4 o;
            o.x = fmaf(acc[i][0].x + b2.x, sc.x, sh.x);
            o.y = fmaf(acc[i][0].y + b2.y, sc.y, sh.y);
            o.z = fmaf(acc[i][1].x + b2.z, sc.z, sh.z);
            o.w = fmaf(acc[i][1].y + b2.w, sc.w, sh.w);
            reinterpret_cast<float4*>(out)[(size_t)node * 32 + lane] = o;
        }
    }
}

// ---------------------------------------------------------------------------
extern "C" void kernel_launch(void* const* d_in, const int* in_sizes, int n_in,
                              void* d_out, int out_size) {
    const float* x    = (const float*)d_in[0];
    const int*   ei   = (const int*)d_in[1];
    const float* ew   = (const float*)d_in[2];
    // d_in[3] = edge_attr (unused by reference)
    const float* Wf1  = (const float*)d_in[4];
    const float* bf1  = (const float*)d_in[5];
    const float* Wf2  = (const float*)d_in[6];
    const float* bf2  = (const float*)d_in[7];
    const float* Wi1  = (const float*)d_in[8];
    const float* bi1  = (const float*)d_in[9];
    const float* Wi2  = (const float*)d_in[10];
    const float* bi2  = (const float*)d_in[11];
    const float* gm   = (const float*)d_in[12];
    const float* bt   = (const float*)d_in[13];
    const float* mn   = (const float*)d_in[14];
    const float* vr   = (const float*)d_in[15];
    float* out = (float*)d_out;

    cudaFuncSetAttribute(k_mlp, cudaFuncAttributeMaxDynamicSharedMemorySize, 98304);

    k_table<<<1, 1024>>>(Wf1, bf1, Wf2, bf2);
    k_zero<<<(NN * HID / 4 + 255) / 256, 256>>>();
    k_scatter<<<1536, 256>>>(x, ei, ew);
    k_mlp<<<(NN + 63) / 64, 256, 98304>>>(Wi1, bi1, Wi2, bi2, gm, bt, mn, vr, out);
}